// round 4
// baseline (speedup 1.0000x reference)
#include <cuda_runtime.h>

// SR_Loss: NN(obj->sr) + ray-triangle parity interior test + reductions.
// Shapes fixed: obj 8192x3, sr 4096x3, verts 4100x3, normals 4096x3, faces 4096x3.
// Output: [pen_dist, cmap(8192)] = 8193 f32.

#define N_OBJ  8192
#define N_SR   4096
#define N_F    4096
#define NPAIR  (N_F / 2)
#define EPSF   1e-8f
#define EPSQ   1e-16f   // EPSF^2

typedef unsigned long long u64;

// ---------------- scratch (device globals; no allocation allowed) ----------
__device__ float4 g_sr4[N_SR];          // sr point + |s|^2
__device__ float4 g_face4[NPAIR * 8];   // pair-interleaved face constants (32 f/pair)
__device__ float4 g_D4[N_OBJ];          // D = trg - obj, plus |D|^2 in .w
__device__ float  g_pen[N_OBJ];         // per-point pen term (interior ? |D|^2 : 0)

// ---------------- f32x2 packed helpers (sm_103a) ---------------------------
__device__ __forceinline__ u64 pk(float lo, float hi) {
    u64 r;
    asm("mov.b64 %0, {%1, %2};" : "=l"(r)
        : "r"(__float_as_uint(lo)), "r"(__float_as_uint(hi)));
    return r;
}
__device__ __forceinline__ void upk(u64 v, float& lo, float& hi) {
    unsigned int a, b;
    asm("mov.b64 {%0, %1}, %2;" : "=r"(a), "=r"(b) : "l"(v));
    lo = __uint_as_float(a);
    hi = __uint_as_float(b);
}
__device__ __forceinline__ u64 f2mul(u64 a, u64 b) {
    u64 r;
    asm("mul.rn.f32x2 %0, %1, %2;" : "=l"(r) : "l"(a), "l"(b));
    return r;
}
__device__ __forceinline__ u64 f2fma(u64 a, u64 b, u64 c) {
    u64 r;
    asm("fma.rn.f32x2 %0, %1, %2, %3;" : "=l"(r) : "l"(a), "l"(b), "l"(c));
    return r;
}

// ---------------- prep: pack sr, precompute face constants -----------------
// Face record (16 floats): n(3), v0.n, c01(3), -v0.c01, c12(3), -v1.c12, c20(3), -v2.c20
// where c_ab = cross(n, vb - va). Stored pair-interleaved: for face pair p,
// scalar slot q lives at float index p*32 + 2*q + (f&1), so one 16B load gives
// two ready-packed f32x2 operands (slots q, q+1 for faces 2p and 2p+1).
__global__ void prep_kernel(const float* __restrict__ sr,
                            const float* __restrict__ hv,
                            const float* __restrict__ fn,
                            const int*   __restrict__ hf) {
    int f = blockIdx.x * blockDim.x + threadIdx.x;
    if (f >= N_F) return;

    // pack sr point (N_SR == N_F)
    float sx = sr[3 * f + 0], sy = sr[3 * f + 1], sz = sr[3 * f + 2];
    g_sr4[f] = make_float4(sx, sy, sz, sx * sx + sy * sy + sz * sz);

    int i0 = hf[3 * f + 0], i1 = hf[3 * f + 1], i2 = hf[3 * f + 2];
    float nx = fn[3 * f + 0], ny = fn[3 * f + 1], nz = fn[3 * f + 2];
    float v0x = hv[3 * i0 + 0], v0y = hv[3 * i0 + 1], v0z = hv[3 * i0 + 2];
    float v1x = hv[3 * i1 + 0], v1y = hv[3 * i1 + 1], v1z = hv[3 * i1 + 2];
    float v2x = hv[3 * i2 + 0], v2y = hv[3 * i2 + 1], v2z = hv[3 * i2 + 2];

    float vals[16];
    vals[0] = nx; vals[1] = ny; vals[2] = nz;
    vals[3] = v0x * nx + v0y * ny + v0z * nz;

    // edge 01: c = cross(n, v1-v0), E = -dot(v0, c)
    {
        float wx = v1x - v0x, wy = v1y - v0y, wz = v1z - v0z;
        float cx = ny * wz - nz * wy;
        float cy = nz * wx - nx * wz;
        float cz = nx * wy - ny * wx;
        vals[4] = cx; vals[5] = cy; vals[6] = cz;
        vals[7] = -(v0x * cx + v0y * cy + v0z * cz);
    }
    // edge 12
    {
        float wx = v2x - v1x, wy = v2y - v1y, wz = v2z - v1z;
        float cx = ny * wz - nz * wy;
        float cy = nz * wx - nx * wz;
        float cz = nx * wy - ny * wx;
        vals[8] = cx; vals[9] = cy; vals[10] = cz;
        vals[11] = -(v1x * cx + v1y * cy + v1z * cz);
    }
    // edge 20
    {
        float wx = v0x - v2x, wy = v0y - v2y, wz = v0z - v2z;
        float cx = ny * wz - nz * wy;
        float cy = nz * wx - nx * wz;
        float cz = nx * wy - ny * wx;
        vals[12] = cx; vals[13] = cy; vals[14] = cz;
        vals[15] = -(v2x * cx + v2y * cy + v2z * cz);
    }

    int p = f >> 1, h = f & 1;
    float* out = reinterpret_cast<float*>(g_face4) + p * 32 + h;
#pragma unroll
    for (int q = 0; q < 16; q++) out[2 * q] = vals[q];
}

// ---------------- NN + cmap + D -------------------------------------------
// One warp per obj point; lanes stride over sr points; shfl reduction with
// first-occurrence (smallest index) tie-break to match jnp.argmin.
__global__ void __launch_bounds__(256) nn_kernel(const float* __restrict__ obj,
                                                 float* __restrict__ out) {
    int wid = threadIdx.x >> 5, lane = threadIdx.x & 31;
    int i = blockIdx.x * 8 + wid;

    float ox = obj[3 * i + 0], oy = obj[3 * i + 1], oz = obj[3 * i + 2];
    float o2 = ox * ox + oy * oy + oz * oz;

    float best = 3.402823466e38f;
    int bj = 0;
#pragma unroll 4
    for (int j = lane; j < N_SR; j += 32) {
        float4 s = __ldg(&g_sr4[j]);
        float dot = ox * s.x + oy * s.y + oz * s.z;
        float d2 = (o2 + s.w) - 2.0f * dot;
        if (d2 < best) { best = d2; bj = j; }
    }
#pragma unroll
    for (int off = 16; off; off >>= 1) {
        float ob = __shfl_down_sync(0xffffffffu, best, off);
        int   oj = __shfl_down_sync(0xffffffffu, bj, off);
        if (ob < best || (ob == best && oj < bj)) { best = ob; bj = oj; }
    }
    if (lane == 0) {
        float4 s = g_sr4[bj];
        float Dx = s.x - ox, Dy = s.y - oy, Dz = s.z - oz;
        float diff2 = Dx * Dx + Dy * Dy + Dz * Dz;
        g_D4[i] = make_float4(Dx, Dy, Dz, diff2);
        float nnd = sqrtf(fmaxf(best, 0.0f));
        // cmap = 1 - 2*(sigmoid(100*nnd)-0.5) = 2/(1+exp(100*nnd))
        out[1 + i] = 2.0f / (1.0f + expf(100.0f * nnd));
    }
}

// ---------------- ray-triangle parity (division-free, f32x2 packed) --------
// Block: 32 obj points (lanes) x 8 warps (disjoint face-pair chunks).
// Per pair of faces per point:
//   num  = v0.n - n.o            denom = n.D
//   base = c.o + E               bd    = c.D
//   q = base*denom + num*bd ; r = q*denom           (sign(r) == sign(s))
//   w = (num - EPS*denom)*denom                     (w>0  <=> t>EPS)
//   dd = denom*denom                                (dd>EPS^2 <=> dmask)
//   hit = (min(r0,r1,r2) >= 0) & (w > 0) & (dd > EPS^2)
__global__ void __launch_bounds__(256, 2) hits_kernel(const float* __restrict__ obj) {
    __shared__ int s_cnt[8][32];
    int wid = threadIdx.x >> 5, lane = threadIdx.x & 31;
    int i = blockIdx.x * 32 + lane;

    float ox = obj[3 * i + 0], oy = obj[3 * i + 1], oz = obj[3 * i + 2];
    float4 D = g_D4[i];

    u64 OX = pk(ox, ox),  OY = pk(oy, oy),  OZ = pk(oz, oz);
    u64 MX = pk(-ox, -ox), MY = pk(-oy, -oy), MZ = pk(-oz, -oz);
    u64 DX = pk(D.x, D.x), DY = pk(D.y, D.y), DZ = pk(D.z, D.z);
    u64 MEPS = pk(-EPSF, -EPSF);

    int cnt = 0;
    // 32 floats = 8 ulonglong2 per face-pair record.
    const ulonglong2* fb =
        reinterpret_cast<const ulonglong2*>(g_face4) + (wid * (NPAIR / 8)) * 8;

#pragma unroll 2
    for (int q = 0; q < NPAIR / 8; q++) {
        const ulonglong2* up = fb + q * 8;
        ulonglong2 t0 = __ldg(up + 0);
        ulonglong2 t1 = __ldg(up + 1);
        ulonglong2 t2 = __ldg(up + 2);
        ulonglong2 t3 = __ldg(up + 3);
        ulonglong2 t4 = __ldg(up + 4);
        ulonglong2 t5 = __ldg(up + 5);
        ulonglong2 t6 = __ldg(up + 6);
        ulonglong2 t7 = __ldg(up + 7);
        u64 NX = t0.x, NY = t0.y, NZ = t1.x, V0N = t1.y;
        u64 AX = t2.x, AY = t2.y, AZ = t3.x, EA  = t3.y;
        u64 BX = t4.x, BY = t4.y, BZ = t5.x, EB  = t5.y;
        u64 CX = t6.x, CY = t6.y, CZ = t7.x, EC  = t7.y;

        u64 num = f2fma(NX, MX, f2fma(NY, MY, f2fma(NZ, MZ, V0N)));
        u64 den = f2fma(NX, DX, f2fma(NY, DY, f2mul(NZ, DZ)));

        u64 ba = f2fma(AX, OX, f2fma(AY, OY, f2fma(AZ, OZ, EA)));
        u64 da = f2fma(AX, DX, f2fma(AY, DY, f2mul(AZ, DZ)));
        u64 ra = f2mul(f2fma(ba, den, f2mul(num, da)), den);

        u64 bb = f2fma(BX, OX, f2fma(BY, OY, f2fma(BZ, OZ, EB)));
        u64 db = f2fma(BX, DX, f2fma(BY, DY, f2mul(BZ, DZ)));
        u64 rb = f2mul(f2fma(bb, den, f2mul(num, db)), den);

        u64 bc = f2fma(CX, OX, f2fma(CY, OY, f2fma(CZ, OZ, EC)));
        u64 dc = f2fma(CX, DX, f2fma(CY, DY, f2mul(CZ, DZ)));
        u64 rc = f2mul(f2fma(bc, den, f2mul(num, dc)), den);

        u64 wv = f2mul(f2fma(MEPS, den, num), den);
        u64 dd = f2mul(den, den);

        float ra0, ra1, rb0, rb1, rc0, rc1, w0, w1, dd0, dd1;
        upk(ra, ra0, ra1);
        upk(rb, rb0, rb1);
        upk(rc, rc0, rc1);
        upk(wv, w0, w1);
        upk(dd, dd0, dd1);

        float m0 = fminf(fminf(ra0, rb0), rc0);
        float m1 = fminf(fminf(ra1, rb1), rc1);
        cnt += (int)((m0 >= 0.0f) & (w0 > 0.0f) & (dd0 > EPSQ));
        cnt += (int)((m1 >= 0.0f) & (w1 > 0.0f) & (dd1 > EPSQ));
    }

    s_cnt[wid][lane] = cnt;
    __syncthreads();
    if (wid == 0) {
        int tot = 0;
#pragma unroll
        for (int k = 0; k < 8; k++) tot += s_cnt[k][lane];
        g_pen[i] = (tot & 1) ? D.w : 0.0f;
    }
}

// ---------------- final deterministic reduction ----------------------------
__global__ void reduce_kernel(float* __restrict__ out) {
    __shared__ float s[256];
    float sum = 0.0f;
    for (int i = threadIdx.x; i < N_OBJ; i += 256) sum += g_pen[i];
    s[threadIdx.x] = sum;
    __syncthreads();
#pragma unroll
    for (int off = 128; off; off >>= 1) {
        if (threadIdx.x < off) s[threadIdx.x] += s[threadIdx.x + off];
        __syncthreads();
    }
    if (threadIdx.x == 0) out[0] = sqrtf(s[0] + 1e-12f);
}

// ---------------- launch ---------------------------------------------------
extern "C" void kernel_launch(void* const* d_in, const int* in_sizes, int n_in,
                              void* d_out, int out_size) {
    const float* obj = (const float*)d_in[0];
    const float* sr  = (const float*)d_in[1];
    const float* hv  = (const float*)d_in[2];
    const float* fn  = (const float*)d_in[3];
    const int*   hf  = (const int*)d_in[4];
    float* out = (float*)d_out;

    prep_kernel<<<(N_F + 255) / 256, 256>>>(sr, hv, fn, hf);
    nn_kernel<<<N_OBJ / 8, 256>>>(obj, out);
    hits_kernel<<<N_OBJ / 32, 256>>>(obj);
    reduce_kernel<<<1, 256>>>(out);
}

// round 5
// speedup vs baseline: 1.0429x; 1.0429x over previous
#include <cuda_runtime.h>

// SR_Loss: NN(obj->sr) + ray-triangle parity interior test + reductions.
// obj 8192x3, sr 4096x3, verts 4100x3, normals 4096x3, faces 4096x3.
// Output: [pen_dist, cmap(8192)] = 8193 f32.
//
// 3 kernels: prep (face constants + sr packing), main (fused NN + parity,
// per-block pen partial), reduce (256 partials -> pen_dist).

#define N_OBJ  8192
#define N_SR   4096
#define N_F    4096
#define NPAIR  (N_F / 2)
#define EPSF   1e-8f
#define EPSQ   1e-16f   // EPSF^2
#define NBLK   (N_OBJ / 32)

typedef unsigned long long u64;

// ---------------- scratch (device globals; no allocation allowed) ----------
__device__ float4 g_sr4[N_SR];          // sr point + |s|^2
__device__ float4 g_face4[NPAIR * 8];   // pair-interleaved face constants (32 f/pair)
__device__ float  g_part[NBLK];         // per-block pen partial sums

// ---------------- f32x2 packed helpers (sm_103a) ---------------------------
__device__ __forceinline__ u64 pk(float lo, float hi) {
    u64 r;
    asm("mov.b64 %0, {%1, %2};" : "=l"(r)
        : "r"(__float_as_uint(lo)), "r"(__float_as_uint(hi)));
    return r;
}
__device__ __forceinline__ void upk(u64 v, float& lo, float& hi) {
    unsigned int a, b;
    asm("mov.b64 {%0, %1}, %2;" : "=r"(a), "=r"(b) : "l"(v));
    lo = __uint_as_float(a);
    hi = __uint_as_float(b);
}
__device__ __forceinline__ u64 f2mul(u64 a, u64 b) {
    u64 r;
    asm("mul.rn.f32x2 %0, %1, %2;" : "=l"(r) : "l"(a), "l"(b));
    return r;
}
__device__ __forceinline__ u64 f2fma(u64 a, u64 b, u64 c) {
    u64 r;
    asm("fma.rn.f32x2 %0, %1, %2, %3;" : "=l"(r) : "l"(a), "l"(b), "l"(c));
    return r;
}

// ---------------- prep: pack sr, precompute face constants -----------------
// Face record (16 floats): n(3), v0.n, c01(3), -v0.c01, c12(3), -v1.c12,
// c20(3), -v2.c20, c_ab = cross(n, vb - va). Pair-interleaved: for pair p,
// slot q at float index p*32 + 2*q + (f&1) -> one 16B load = two f32x2 operands.
__global__ void prep_kernel(const float* __restrict__ sr,
                            const float* __restrict__ hv,
                            const float* __restrict__ fn,
                            const int*   __restrict__ hf) {
    int f = blockIdx.x * blockDim.x + threadIdx.x;
    if (f >= N_F) return;

    float sx = sr[3 * f + 0], sy = sr[3 * f + 1], sz = sr[3 * f + 2];
    g_sr4[f] = make_float4(sx, sy, sz, sx * sx + sy * sy + sz * sz);

    int i0 = hf[3 * f + 0], i1 = hf[3 * f + 1], i2 = hf[3 * f + 2];
    float nx = fn[3 * f + 0], ny = fn[3 * f + 1], nz = fn[3 * f + 2];
    float v0x = hv[3 * i0 + 0], v0y = hv[3 * i0 + 1], v0z = hv[3 * i0 + 2];
    float v1x = hv[3 * i1 + 0], v1y = hv[3 * i1 + 1], v1z = hv[3 * i1 + 2];
    float v2x = hv[3 * i2 + 0], v2y = hv[3 * i2 + 1], v2z = hv[3 * i2 + 2];

    float vals[16];
    vals[0] = nx; vals[1] = ny; vals[2] = nz;
    vals[3] = v0x * nx + v0y * ny + v0z * nz;
    {
        float wx = v1x - v0x, wy = v1y - v0y, wz = v1z - v0z;
        float cx = ny * wz - nz * wy, cy = nz * wx - nx * wz, cz = nx * wy - ny * wx;
        vals[4] = cx; vals[5] = cy; vals[6] = cz;
        vals[7] = -(v0x * cx + v0y * cy + v0z * cz);
    }
    {
        float wx = v2x - v1x, wy = v2y - v1y, wz = v2z - v1z;
        float cx = ny * wz - nz * wy, cy = nz * wx - nx * wz, cz = nx * wy - ny * wx;
        vals[8] = cx; vals[9] = cy; vals[10] = cz;
        vals[11] = -(v1x * cx + v1y * cy + v1z * cz);
    }
    {
        float wx = v0x - v2x, wy = v0y - v2y, wz = v0z - v2z;
        float cx = ny * wz - nz * wy, cy = nz * wx - nx * wz, cz = nx * wy - ny * wx;
        vals[12] = cx; vals[13] = cy; vals[14] = cz;
        vals[15] = -(v2x * cx + v2y * cy + v2z * cz);
    }

    int p = f >> 1, h = f & 1;
    float* out = reinterpret_cast<float*>(g_face4) + p * 32 + h;
#pragma unroll
    for (int q = 0; q < 16; q++) out[2 * q] = vals[q];
}

// ---------------- main: fused NN + cmap + parity + pen partial -------------
// Block = 32 obj points. Phase A: each of 8 warps does NN for 4 points
// (lanes stride sr; 1 float4 load amortized over 4 points). Phase B: lanes =
// points, warps split the 2048 face-pair records; division-free sign tests in
// f32x2 (2 faces/lane-op). Per-block pen partial -> g_part.
__global__ void __launch_bounds__(256, 2) main_kernel(const float* __restrict__ obj,
                                                      float* __restrict__ out) {
    __shared__ float4 s_po[32];   // point o, .w = unused
    __shared__ float4 s_pd[32];   // D = trg - o, .w = |D|^2
    __shared__ int    s_cnt[8][32];

    int wid = threadIdx.x >> 5, lane = threadIdx.x & 31;
    int pbase = blockIdx.x * 32 + wid * 4;

    // ---- Phase A: NN for 4 points per warp ----
    float ox0 = obj[3 * (pbase + 0) + 0], oy0 = obj[3 * (pbase + 0) + 1], oz0 = obj[3 * (pbase + 0) + 2];
    float ox1 = obj[3 * (pbase + 1) + 0], oy1 = obj[3 * (pbase + 1) + 1], oz1 = obj[3 * (pbase + 1) + 2];
    float ox2 = obj[3 * (pbase + 2) + 0], oy2 = obj[3 * (pbase + 2) + 1], oz2 = obj[3 * (pbase + 2) + 2];
    float ox3 = obj[3 * (pbase + 3) + 0], oy3 = obj[3 * (pbase + 3) + 1], oz3 = obj[3 * (pbase + 3) + 2];
    float o20 = ox0 * ox0 + oy0 * oy0 + oz0 * oz0;
    float o21 = ox1 * ox1 + oy1 * oy1 + oz1 * oz1;
    float o22 = ox2 * ox2 + oy2 * oy2 + oz2 * oz2;
    float o23 = ox3 * ox3 + oy3 * oy3 + oz3 * oz3;

    float b0 = 3.402823466e38f, b1 = b0, b2 = b0, b3 = b0;
    int j0 = 0, j1 = 0, j2 = 0, j3 = 0;

#pragma unroll 4
    for (int j = lane; j < N_SR; j += 32) {
        float4 s = __ldg(&g_sr4[j]);
        float d0 = fmaf(-2.0f, ox0 * s.x + fmaf(oy0, s.y, oz0 * s.z), o20 + s.w);
        float d1 = fmaf(-2.0f, ox1 * s.x + fmaf(oy1, s.y, oz1 * s.z), o21 + s.w);
        float d2 = fmaf(-2.0f, ox2 * s.x + fmaf(oy2, s.y, oz2 * s.z), o22 + s.w);
        float d3 = fmaf(-2.0f, ox3 * s.x + fmaf(oy3, s.y, oz3 * s.z), o23 + s.w);
        if (d0 < b0) { b0 = d0; j0 = j; }
        if (d1 < b1) { b1 = d1; j1 = j; }
        if (d2 < b2) { b2 = d2; j2 = j; }
        if (d3 < b3) { b3 = d3; j3 = j; }
    }
#pragma unroll
    for (int off = 16; off; off >>= 1) {
        float t; int tj;
        t = __shfl_down_sync(~0u, b0, off); tj = __shfl_down_sync(~0u, j0, off);
        if (t < b0 || (t == b0 && tj < j0)) { b0 = t; j0 = tj; }
        t = __shfl_down_sync(~0u, b1, off); tj = __shfl_down_sync(~0u, j1, off);
        if (t < b1 || (t == b1 && tj < j1)) { b1 = t; j1 = tj; }
        t = __shfl_down_sync(~0u, b2, off); tj = __shfl_down_sync(~0u, j2, off);
        if (t < b2 || (t == b2 && tj < j2)) { b2 = t; j2 = tj; }
        t = __shfl_down_sync(~0u, b3, off); tj = __shfl_down_sync(~0u, j3, off);
        if (t < b3 || (t == b3 && tj < j3)) { b3 = t; j3 = tj; }
    }

    if (lane == 0) {
        float obx[4] = {ox0, ox1, ox2, ox3};
        float oby[4] = {oy0, oy1, oy2, oy3};
        float obz[4] = {oz0, oz1, oz2, oz3};
        float bb[4] = {b0, b1, b2, b3};
        int   jj[4] = {j0, j1, j2, j3};
#pragma unroll
        for (int k = 0; k < 4; k++) {
            float4 s = g_sr4[jj[k]];
            float Dx = s.x - obx[k], Dy = s.y - oby[k], Dz = s.z - obz[k];
            s_po[wid * 4 + k] = make_float4(obx[k], oby[k], obz[k], 0.0f);
            s_pd[wid * 4 + k] = make_float4(Dx, Dy, Dz, Dx * Dx + Dy * Dy + Dz * Dz);
            float nnd = sqrtf(fmaxf(bb[k], 0.0f));
            out[1 + pbase + k] = 2.0f / (1.0f + expf(100.0f * nnd));
        }
    }
    __syncthreads();

    // ---- Phase B: parity over faces (division-free, f32x2, 2 faces/op) ----
    float4 po = s_po[lane];
    float4 pd = s_pd[lane];

    u64 OX = pk(po.x, po.x), OY = pk(po.y, po.y), OZ = pk(po.z, po.z);
    u64 MX = pk(-po.x, -po.x), MY = pk(-po.y, -po.y), MZ = pk(-po.z, -po.z);
    u64 DX = pk(pd.x, pd.x), DY = pk(pd.y, pd.y), DZ = pk(pd.z, pd.z);
    u64 MEPS = pk(-EPSF, -EPSF);

    int cnt = 0;
    const ulonglong2* fb =
        reinterpret_cast<const ulonglong2*>(g_face4) + (wid * (NPAIR / 8)) * 8;

#pragma unroll 2
    for (int q = 0; q < NPAIR / 8; q++) {
        const ulonglong2* up = fb + q * 8;
        ulonglong2 t0 = __ldg(up + 0);
        ulonglong2 t1 = __ldg(up + 1);
        ulonglong2 t2 = __ldg(up + 2);
        ulonglong2 t3 = __ldg(up + 3);
        ulonglong2 t4 = __ldg(up + 4);
        ulonglong2 t5 = __ldg(up + 5);
        ulonglong2 t6 = __ldg(up + 6);
        ulonglong2 t7 = __ldg(up + 7);
        u64 NX = t0.x, NY = t0.y, NZ = t1.x, V0N = t1.y;
        u64 AX = t2.x, AY = t2.y, AZ = t3.x, EA  = t3.y;
        u64 BX = t4.x, BY = t4.y, BZ = t5.x, EB  = t5.y;
        u64 CX = t6.x, CY = t6.y, CZ = t7.x, EC  = t7.y;

        u64 num = f2fma(NX, MX, f2fma(NY, MY, f2fma(NZ, MZ, V0N)));
        u64 den = f2fma(NX, DX, f2fma(NY, DY, f2mul(NZ, DZ)));

        u64 ba = f2fma(AX, OX, f2fma(AY, OY, f2fma(AZ, OZ, EA)));
        u64 da = f2fma(AX, DX, f2fma(AY, DY, f2mul(AZ, DZ)));
        u64 ra = f2mul(f2fma(ba, den, f2mul(num, da)), den);

        u64 bb_ = f2fma(BX, OX, f2fma(BY, OY, f2fma(BZ, OZ, EB)));
        u64 db = f2fma(BX, DX, f2fma(BY, DY, f2mul(BZ, DZ)));
        u64 rb = f2mul(f2fma(bb_, den, f2mul(num, db)), den);

        u64 bc = f2fma(CX, OX, f2fma(CY, OY, f2fma(CZ, OZ, EC)));
        u64 dc = f2fma(CX, DX, f2fma(CY, DY, f2mul(CZ, DZ)));
        u64 rc = f2mul(f2fma(bc, den, f2mul(num, dc)), den);

        u64 wv = f2mul(f2fma(MEPS, den, num), den);
        u64 dd = f2mul(den, den);

        float ra0, ra1, rb0, rb1, rc0, rc1, w0, w1, dd0, dd1;
        upk(ra, ra0, ra1);
        upk(rb, rb0, rb1);
        upk(rc, rc0, rc1);
        upk(wv, w0, w1);
        upk(dd, dd0, dd1);

        float m0 = fminf(fminf(ra0, rb0), rc0);
        float m1 = fminf(fminf(ra1, rb1), rc1);
        cnt += (m0 >= 0.0f && w0 > 0.0f && dd0 > EPSQ) ? 1 : 0;
        cnt += (m1 >= 0.0f && w1 > 0.0f && dd1 > EPSQ) ? 1 : 0;
    }

    s_cnt[wid][lane] = cnt;
    __syncthreads();

    if (wid == 0) {
        int tot = 0;
#pragma unroll
        for (int k = 0; k < 8; k++) tot += s_cnt[k][lane];
        float pen = (tot & 1) ? s_pd[lane].w : 0.0f;
#pragma unroll
        for (int off = 16; off; off >>= 1)
            pen += __shfl_down_sync(~0u, pen, off);
        if (lane == 0) g_part[blockIdx.x] = pen;
    }
}

// ---------------- final deterministic reduction (256 partials) -------------
__global__ void reduce_kernel(float* __restrict__ out) {
    __shared__ float s[256];
    s[threadIdx.x] = g_part[threadIdx.x];
    __syncthreads();
#pragma unroll
    for (int off = 128; off; off >>= 1) {
        if (threadIdx.x < off) s[threadIdx.x] += s[threadIdx.x + off];
        __syncthreads();
    }
    if (threadIdx.x == 0) out[0] = sqrtf(s[0] + 1e-12f);
}

// ---------------- launch ---------------------------------------------------
extern "C" void kernel_launch(void* const* d_in, const int* in_sizes, int n_in,
                              void* d_out, int out_size) {
    const float* obj = (const float*)d_in[0];
    const float* sr  = (const float*)d_in[1];
    const float* hv  = (const float*)d_in[2];
    const float* fn  = (const float*)d_in[3];
    const int*   hf  = (const int*)d_in[4];
    float* out = (float*)d_out;

    prep_kernel<<<(N_F + 255) / 256, 256>>>(sr, hv, fn, hf);
    main_kernel<<<NBLK, 256>>>(obj, out);
    reduce_kernel<<<1, 256>>>(out);
}